// round 8
// baseline (speedup 1.0000x reference)
#include <cuda_runtime.h>
#include <cuda_bf16.h>
#include <math.h>

#define NN_MAX 50000
#define EE_MAX 600000
#define DD 128
#define HH 4
#define CC 32
#define NEG_SLOPE 0.2f
#define LN_EPS 1e-5f
#define NB_MAX 256

// ---------------- device scratch ----------------
static __device__ float g_h[NN_MAX * DD];
static __device__ float g_asrc[NN_MAX * HH];
static __device__ float g_adst[NN_MAX * HH];
static __device__ int   g_deg[NN_MAX];
static __device__ int   g_rowoff[NN_MAX];
static __device__ int   g_cursor[NN_MAX];
static __device__ int   g_srclist[EE_MAX];
static __device__ int   g_bsum[NB_MAX];
static __device__ int   g_is64;

// ---------------- f32x2 helpers ----------------
__device__ __forceinline__ unsigned long long pk2(float lo, float hi) {
    unsigned long long r;
    asm("mov.b64 %0, {%1, %2};" : "=l"(r) : "f"(lo), "f"(hi));
    return r;
}
__device__ __forceinline__ unsigned long long fma2(unsigned long long a,
                                                   unsigned long long b,
                                                   unsigned long long c) {
    unsigned long long d;
    asm("fma.rn.f32x2 %0, %1, %2, %3;" : "=l"(d) : "l"(a), "l"(b), "l"(c));
    return d;
}
__device__ __forceinline__ float2 upk2(unsigned long long v) {
    float lo, hi;
    asm("mov.b64 {%0, %1}, %2;" : "=f"(lo), "=f"(hi) : "l"(v));
    return make_float2(lo, hi);
}
__device__ __forceinline__ float lrelu(float v) {
    return (v > 0.f) ? v : v * NEG_SLOPE;
}

// ---------------- Kernel 0: zero degrees + detect dtype ----------------
__global__ void detect_zero_kernel(const int* __restrict__ ei32, int E, int n)
{
    int i = blockIdx.x * 256 + threadIdx.x;
    if (i < n) g_deg[i] = 0;
    if (blockIdx.x == 0) {
        int checks = 2 * E; if (checks > 4096) checks = 4096;
        int nz = 0;
        for (int j = threadIdx.x; j < checks; j += 256)
            if (ei32[2 * j + 1] != 0) nz = 1;
        #pragma unroll
        for (int o = 16; o >= 1; o >>= 1)
            nz |= __shfl_xor_sync(0xffffffffu, nz, o);
        __shared__ int s_nz[8];
        if ((threadIdx.x & 31) == 0) s_nz[threadIdx.x >> 5] = nz;
        __syncthreads();
        if (threadIdx.x == 0) {
            int a = 0;
            for (int w = 0; w < 8; w++) a |= s_nz[w];
            g_is64 = (a == 0) ? 1 : 0;
        }
    }
}

__device__ __forceinline__ int edge_src(const void* ei, int E, int e) {
    if (g_is64) return (int)((const long long*)ei)[e];
    return ((const int*)ei)[e];
}
__device__ __forceinline__ int edge_dst(const void* ei, int E, int e) {
    if (g_is64) return (int)((const long long*)ei)[E + e];
    return ((const int*)ei)[E + e];
}

// ---------------- Kernel 1: h = x @ W + fused attention logits ----------
// v3: x rows live in registers (8 x float4 per thread, loaded directly from
// global); broadcast via __shfl_sync. Only W is staged in smem (64KB).
// Crossbar traffic per k drops from 12 cyc/warp to 4 -> FMA-pipe bound.
__global__ __launch_bounds__(256, 2)
void gemm_kernel(const float* __restrict__ x, const float* __restrict__ W,
                 const float* __restrict__ att_src, const float* __restrict__ att_dst,
                 int n)
{
    extern __shared__ float ws[];          // [128][128] = 64KB

    int tid = threadIdx.x;
    int rowbase = blockIdx.x * 64;
    int rg = tid >> 5;    // warp: 8-row group
    int cg = tid & 31;    // lane: 4-col group

    // Stage W
    const float4* W4 = (const float4*)W;
    float4* ws4 = (float4*)ws;
    #pragma unroll
    for (int t = tid; t < 4096; t += 256) ws4[t] = W4[t];

    // Load this warp's 8 x-rows into registers (lane cg covers k=4cg..4cg+3)
    const float4* x4in = (const float4*)x;
    float4 xr[8];
    #pragma unroll
    for (int r = 0; r < 8; r++) {
        int grow = rowbase + rg * 8 + r;
        xr[r] = (grow < n) ? x4in[grow * 32 + cg]
                           : make_float4(0.f, 0.f, 0.f, 0.f);
    }
    __syncthreads();

    unsigned long long acc0[8], acc1[8];
    #pragma unroll
    for (int i = 0; i < 8; i++) { acc0[i] = 0ull; acc1[i] = 0ull; }

    const ulonglong2* ws2 = (const ulonglong2*)ws;

    #pragma unroll 2
    for (int k4 = 0; k4 < 32; k4++) {
        ulonglong2 wv0 = ws2[(k4 * 4 + 0) * 32 + cg];
        ulonglong2 wv1 = ws2[(k4 * 4 + 1) * 32 + cg];
        ulonglong2 wv2 = ws2[(k4 * 4 + 2) * 32 + cg];
        ulonglong2 wv3 = ws2[(k4 * 4 + 3) * 32 + cg];
        #pragma unroll
        for (int r = 0; r < 8; r++) {
            float xv0 = __shfl_sync(0xffffffffu, xr[r].x, k4);
            float xv1 = __shfl_sync(0xffffffffu, xr[r].y, k4);
            float xv2 = __shfl_sync(0xffffffffu, xr[r].z, k4);
            float xv3 = __shfl_sync(0xffffffffu, xr[r].w, k4);
            unsigned long long p0 = pk2(xv0, xv0);
            unsigned long long p1 = pk2(xv1, xv1);
            unsigned long long p2 = pk2(xv2, xv2);
            unsigned long long p3 = pk2(xv3, xv3);
            acc0[r] = fma2(p0, wv0.x, acc0[r]); acc1[r] = fma2(p0, wv0.y, acc1[r]);
            acc0[r] = fma2(p1, wv1.x, acc0[r]); acc1[r] = fma2(p1, wv1.y, acc1[r]);
            acc0[r] = fma2(p2, wv2.x, acc0[r]); acc1[r] = fma2(p2, wv2.y, acc1[r]);
            acc0[r] = fma2(p3, wv3.x, acc0[r]); acc1[r] = fma2(p3, wv3.y, acc1[r]);
        }
    }

    // Epilogue: store h + per-node attention logits
    float4 as4 = ((const float4*)att_src)[cg];
    float4 ad4 = ((const float4*)att_dst)[cg];
    float4* h4 = (float4*)g_h;
    int head = cg >> 3;

    #pragma unroll
    for (int i = 0; i < 8; i++) {
        float2 a = upk2(acc0[i]);
        float2 b = upk2(acc1[i]);
        float4 hv = make_float4(a.x, a.y, b.x, b.y);
        float ps = hv.x * as4.x + hv.y * as4.y + hv.z * as4.z + hv.w * as4.w;
        float pd = hv.x * ad4.x + hv.y * ad4.y + hv.z * ad4.z + hv.w * ad4.w;
        #pragma unroll
        for (int o = 4; o >= 1; o >>= 1) {
            ps += __shfl_xor_sync(0xffffffffu, ps, o);
            pd += __shfl_xor_sync(0xffffffffu, pd, o);
        }
        int grow = rowbase + rg * 8 + i;
        if (grow < n) {
            h4[grow * 32 + cg] = hv;
            if ((cg & 7) == 0) {
                g_asrc[grow * HH + head] = ps;
                g_adst[grow * HH + head] = pd;
            }
        }
    }
}

// ---------------- Kernel 2: histogram of dst ----------------
__global__ void hist_kernel(const void* __restrict__ ei, int E)
{
    int e = blockIdx.x * 256 + threadIdx.x;
    if (e < E) atomicAdd(&g_deg[edge_dst(ei, E, e)], 1);
}

// ---------------- Kernel 3a: per-block local exclusive scan -------------
__global__ __launch_bounds__(256)
void scan_local_kernel(int n)
{
    int i = blockIdx.x * 256 + threadIdx.x;
    int lane = threadIdx.x & 31;
    int wid  = threadIdx.x >> 5;
    int v = (i < n) ? g_deg[i] : 0;
    int inc = v;
    #pragma unroll
    for (int o = 1; o < 32; o <<= 1) {
        int t = __shfl_up_sync(0xffffffffu, inc, o);
        if (lane >= o) inc += t;
    }
    __shared__ int wsum[8];
    if (lane == 31) wsum[wid] = inc;
    __syncthreads();
    if (wid == 0) {
        int ws = (lane < 8) ? wsum[lane] : 0;
        #pragma unroll
        for (int o = 1; o < 8; o <<= 1) {
            int t = __shfl_up_sync(0xffffffffu, ws, o);
            if (lane >= o) ws += t;
        }
        if (lane < 8) wsum[lane] = ws;
    }
    __syncthreads();
    int warpbase = (wid == 0) ? 0 : wsum[wid - 1];
    int excl = warpbase + inc - v;
    if (i < n) g_rowoff[i] = excl;
    if (threadIdx.x == 255) g_bsum[blockIdx.x] = warpbase + inc;
}

// ---------------- Kernel 3b: fixup ----------------
__global__ __launch_bounds__(256)
void scan_fixup_kernel(int n, int nb)
{
    __shared__ int s_base;
    if (threadIdx.x < 32) {
        int b = 0;
        for (int j = threadIdx.x; j < blockIdx.x; j += 32) b += g_bsum[j];
        #pragma unroll
        for (int o = 16; o >= 1; o >>= 1)
            b += __shfl_xor_sync(0xffffffffu, b, o);
        if (threadIdx.x == 0) s_base = b;
    }
    __syncthreads();
    int i = blockIdx.x * 256 + threadIdx.x;
    if (i < n) {
        int r = g_rowoff[i] + s_base;
        g_rowoff[i] = r;
        g_cursor[i] = r;
    }
}

// ---------------- Kernel 4: scatter edges into CSR ----------------
__global__ void scatter_kernel(const void* __restrict__ ei, int E)
{
    int e = blockIdx.x * 256 + threadIdx.x;
    if (e < E) {
        int s = edge_src(ei, E, e);
        int d = edge_dst(ei, E, e);
        int pos = atomicAdd(&g_cursor[d], 1);
        g_srclist[pos] = s;
    }
}

// ---------------- Kernel 5: fused softmax-agg + GELU + LN + residual ----
// (R3/R4 proven version — 2 independent FMA chains)
__global__ __launch_bounds__(256)
void agg_ln_kernel(const float* __restrict__ x,
                   const float* __restrict__ bias,
                   const float* __restrict__ gamma,
                   const float* __restrict__ beta,
                   float* __restrict__ out, int n)
{
    int node = blockIdx.x * 8 + (threadIdx.x >> 5);
    if (node >= n) return;
    int lane = threadIdx.x & 31;
    int hd8 = lane >> 3;
    int hd4 = lane & 3;
    int esub = lane >> 2;

    int beg = g_rowoff[node];
    int cnt = g_deg[node];

    float aself = g_asrc[node * HH + hd4];
    float adst4 = g_adst[node * HH + hd4];

    // Phase A: per-head max of a_src over {self} U neighbors
    float mx = aself;
    for (int k0 = 0; k0 < cnt; k0 += 8) {
        int k = k0 + esub;
        float v = -1e30f;
        if (k < cnt) {
            int s = g_srclist[beg + k];
            v = g_asrc[s * HH + hd4];
        }
        mx = fmaxf(mx, v);
    }
    mx = fmaxf(mx, __shfl_xor_sync(0xffffffffu, mx, 4));
    mx = fmaxf(mx, __shfl_xor_sync(0xffffffffu, mx, 8));
    mx = fmaxf(mx, __shfl_xor_sync(0xffffffffu, mx, 16));

    float mxh    = __shfl_sync(0xffffffffu, mx, hd8);
    float adst   = __shfl_sync(0xffffffffu, adst4, hd8);
    float aselfh = __shfl_sync(0xffffffffu, aself, hd8);
    float M = lrelu(mxh + adst);

    // Phase B: weighted aggregation
    const float4* h4 = (const float4*)g_h;
    float p0 = __expf(lrelu(aselfh + adst) - M);
    float4 hv = h4[node * 32 + lane];
    float4 accA = make_float4(p0 * hv.x, p0 * hv.y, p0 * hv.z, p0 * hv.w);
    float4 accB = make_float4(0.f, 0.f, 0.f, 0.f);
    float dA = p0, dB = 0.f;

    int k = 0;
    for (; k + 2 <= cnt; k += 2) {
        int sa = g_srclist[beg + k];
        int sb = g_srclist[beg + k + 1];
        float ea = g_asrc[sa * HH + hd8];
        float eb = g_asrc[sb * HH + hd8];
        float4 ha = h4[sa * 32 + lane];
        float4 hb = h4[sb * 32 + lane];
        float pa = __expf(lrelu(ea + adst) - M);
        float pb = __expf(lrelu(eb + adst) - M);
        dA += pa; dB += pb;
        accA.x = fmaf(pa, ha.x, accA.x); accA.y = fmaf(pa, ha.y, accA.y);
        accA.z = fmaf(pa, ha.z, accA.z); accA.w = fmaf(pa, ha.w, accA.w);
        accB.x = fmaf(pb, hb.x, accB.x); accB.y = fmaf(pb, hb.y, accB.y);
        accB.z = fmaf(pb, hb.z, accB.z); accB.w = fmaf(pb, hb.w, accB.w);
    }
    if (k < cnt) {
        int sa = g_srclist[beg + k];
        float ea = g_asrc[sa * HH + hd8];
        float4 ha = h4[sa * 32 + lane];
        float pa = __expf(lrelu(ea + adst) - M);
        dA += pa;
        accA.x = fmaf(pa, ha.x, accA.x); accA.y = fmaf(pa, ha.y, accA.y);
        accA.z = fmaf(pa, ha.z, accA.z); accA.w = fmaf(pa, ha.w, accA.w);
    }

    float denom = dA + dB;
    float inv = 1.0f / denom;
    float4 bi = ((const float4*)bias)[lane];
    float4 o = make_float4(fmaf(accA.x + accB.x, inv, bi.x),
                           fmaf(accA.y + accB.y, inv, bi.y),
                           fmaf(accA.z + accB.z, inv, bi.z),
                           fmaf(accA.w + accB.w, inv, bi.w));

    const float RS2 = 0.70710678118654752f;
    float4 f;
    f.x = 0.5f * o.x * (1.0f + erff(o.x * RS2));
    f.y = 0.5f * o.y * (1.0f + erff(o.y * RS2));
    f.z = 0.5f * o.z * (1.0f + erff(o.z * RS2));
    f.w = 0.5f * o.w * (1.0f + erff(o.w * RS2));

    float s1 = f.x + f.y + f.z + f.w;
    float s2 = f.x * f.x + f.y * f.y + f.z * f.z + f.w * f.w;
    #pragma unroll
    for (int off = 16; off >= 1; off >>= 1) {
        s1 += __shfl_xor_sync(0xffffffffu, s1, off);
        s2 += __shfl_xor_sync(0xffffffffu, s2, off);
    }
    float mu  = s1 * (1.0f / 128.0f);
    float var = s2 * (1.0f / 128.0f) - mu * mu;
    float r = rsqrtf(var + LN_EPS);

    float4 gm = ((const float4*)gamma)[lane];
    float4 bt = ((const float4*)beta)[lane];
    float4 xv = ((const float4*)x)[node * 32 + lane];
    float4 res;
    res.x = (f.x - mu) * r * gm.x + bt.x + xv.x;
    res.y = (f.y - mu) * r * gm.y + bt.y + xv.y;
    res.z = (f.z - mu) * r * gm.z + bt.z + xv.z;
    res.w = (f.w - mu) * r * gm.w + bt.w + xv.w;
    ((float4*)out)[node * 32 + lane] = res;
}

// ---------------- launch ----------------
extern "C" void kernel_launch(void* const* d_in, const int* in_sizes, int n_in,
                              void* d_out, int out_size)
{
    const float* x       = (const float*)d_in[0];
    const void*  ei      = d_in[1];
    const float* W       = (const float*)d_in[2];
    const float* att_src = (const float*)d_in[3];
    const float* att_dst = (const float*)d_in[4];
    const float* bias    = (const float*)d_in[5];
    const float* gamma   = (const float*)d_in[6];
    const float* beta    = (const float*)d_in[7];
    float*       out     = (float*)d_out;

    int n = in_sizes[0] / DD;     // 50000
    int E = in_sizes[1] / 2;      // 600000
    int nb = (n + 255) / 256;     // 196

    const int GEMM_SMEM = 128 * 128 * 4;   // 64KB (W only)
    cudaFuncSetAttribute(gemm_kernel, cudaFuncAttributeMaxDynamicSharedMemorySize, GEMM_SMEM);

    detect_zero_kernel<<<nb, 256>>>((const int*)ei, E, n);
    gemm_kernel<<<(n + 63) / 64, 256, GEMM_SMEM>>>(x, W, att_src, att_dst, n);
    hist_kernel<<<(E + 255) / 256, 256>>>(ei, E);
    scan_local_kernel<<<nb, 256>>>(n);
    scan_fixup_kernel<<<nb, 256>>>(n, nb);
    scatter_kernel<<<(E + 255) / 256, 256>>>(ei, E);
    agg_ln_kernel<<<(n + 7) / 8, 256>>>(x, bias, gamma, beta, out, n);
}

// round 9
// speedup vs baseline: 1.0734x; 1.0734x over previous
#include <cuda_runtime.h>
#include <cuda_bf16.h>
#include <math.h>

#define NN_MAX 50000
#define EE_MAX 600000
#define DD 128
#define HH 4
#define CC 32
#define NEG_SLOPE 0.2f
#define LN_EPS 1e-5f
#define NB_MAX 256

// ---------------- device scratch ----------------
static __device__ float g_h[NN_MAX * DD];
static __device__ float g_asrc[NN_MAX * HH];
static __device__ float g_adst[NN_MAX * HH];
static __device__ int   g_deg[NN_MAX];
static __device__ int   g_rowoff[NN_MAX];
static __device__ int   g_cursor[NN_MAX];
static __device__ int   g_srclist[EE_MAX];
static __device__ int   g_bsum[NB_MAX];
static __device__ int   g_is64;

// ---------------- f32x2 helpers ----------------
__device__ __forceinline__ unsigned long long pk2(float lo, float hi) {
    unsigned long long r;
    asm("mov.b64 %0, {%1, %2};" : "=l"(r) : "f"(lo), "f"(hi));
    return r;
}
__device__ __forceinline__ unsigned long long fma2(unsigned long long a,
                                                   unsigned long long b,
                                                   unsigned long long c) {
    unsigned long long d;
    asm("fma.rn.f32x2 %0, %1, %2, %3;" : "=l"(d) : "l"(a), "l"(b), "l"(c));
    return d;
}
__device__ __forceinline__ float2 upk2(unsigned long long v) {
    float lo, hi;
    asm("mov.b64 {%0, %1}, %2;" : "=f"(lo), "=f"(hi) : "l"(v));
    return make_float2(lo, hi);
}
__device__ __forceinline__ float lrelu(float v) {
    return (v > 0.f) ? v : v * NEG_SLOPE;
}

// ---------------- Kernel 0: zero degrees + detect dtype ----------------
__global__ void detect_zero_kernel(const int* __restrict__ ei32, int E, int n)
{
    int i = blockIdx.x * 256 + threadIdx.x;
    if (i < n) g_deg[i] = 0;
    if (blockIdx.x == 0) {
        int checks = 2 * E; if (checks > 4096) checks = 4096;
        int nz = 0;
        for (int j = threadIdx.x; j < checks; j += 256)
            if (ei32[2 * j + 1] != 0) nz = 1;
        #pragma unroll
        for (int o = 16; o >= 1; o >>= 1)
            nz |= __shfl_xor_sync(0xffffffffu, nz, o);
        __shared__ int s_nz[8];
        if ((threadIdx.x & 31) == 0) s_nz[threadIdx.x >> 5] = nz;
        __syncthreads();
        if (threadIdx.x == 0) {
            int a = 0;
            for (int w = 0; w < 8; w++) a |= s_nz[w];
            g_is64 = (a == 0) ? 1 : 0;
        }
    }
}

__device__ __forceinline__ int edge_src(const void* ei, int E, int e) {
    if (g_is64) return (int)((const long long*)ei)[e];
    return ((const int*)ei)[e];
}
__device__ __forceinline__ int edge_dst(const void* ei, int E, int e) {
    if (g_is64) return (int)((const long long*)ei)[E + e];
    return ((const int*)ei)[E + e];
}

// ---------------- Kernel 1: h = x @ W + fused attention logits ----------
// v1b: R4-proven structure; ONLY change = x read as one LDS.128 broadcast
// per row per k4 (was 4 scalar LDS.32 broadcasts). Crossbar wavefronts per
// k4 drop 48 -> 24 vs 64 FFMA2 -> FMA-pipe bound.
__global__ __launch_bounds__(256, 2)
void gemm_kernel(const float* __restrict__ x, const float* __restrict__ W,
                 const float* __restrict__ att_src, const float* __restrict__ att_dst,
                 int n)
{
    extern __shared__ float smem[];
    float* ws = smem;              // [128][128] = 64KB
    float* xs = smem + 128 * 128;  // [64][128]  = 32KB

    int rowbase = blockIdx.x * 64;

    const float4* W4 = (const float4*)W;
    float4* ws4 = (float4*)ws;
    #pragma unroll
    for (int t = threadIdx.x; t < 4096; t += 256) ws4[t] = W4[t];

    float4* xs4 = (float4*)xs;
    const float4* x4in = (const float4*)x;
    #pragma unroll
    for (int t = threadIdx.x; t < 2048; t += 256) {
        int r = t >> 5, k4 = t & 31;
        int grow = rowbase + r;
        float4 v = make_float4(0.f, 0.f, 0.f, 0.f);
        if (grow < n) v = x4in[grow * 32 + k4];
        xs4[r * 32 + k4] = v;
    }
    __syncthreads();

    int rg = threadIdx.x >> 5;
    int cg = threadIdx.x & 31;

    unsigned long long acc0[8], acc1[8];
    #pragma unroll
    for (int i = 0; i < 8; i++) { acc0[i] = 0ull; acc1[i] = 0ull; }

    const float* xrow = xs + rg * 8 * 128;
    const ulonglong2* ws2 = (const ulonglong2*)ws;

    #pragma unroll 4
    for (int k4 = 0; k4 < 32; k4++) {
        ulonglong2 wv0 = ws2[(k4 * 4 + 0) * 32 + cg];
        ulonglong2 wv1 = ws2[(k4 * 4 + 1) * 32 + cg];
        ulonglong2 wv2 = ws2[(k4 * 4 + 2) * 32 + cg];
        ulonglong2 wv3 = ws2[(k4 * 4 + 3) * 32 + cg];
        #pragma unroll
        for (int i = 0; i < 8; i++) {
            // one LDS.128 broadcast: 4 k-values of row i
            float4 xv = *(const float4*)(xrow + i * 128 + k4 * 4);
            unsigned long long p0 = pk2(xv.x, xv.x);
            unsigned long long p1 = pk2(xv.y, xv.y);
            unsigned long long p2 = pk2(xv.z, xv.z);
            unsigned long long p3 = pk2(xv.w, xv.w);
            acc0[i] = fma2(p0, wv0.x, acc0[i]); acc1[i] = fma2(p0, wv0.y, acc1[i]);
            acc0[i] = fma2(p1, wv1.x, acc0[i]); acc1[i] = fma2(p1, wv1.y, acc1[i]);
            acc0[i] = fma2(p2, wv2.x, acc0[i]); acc1[i] = fma2(p2, wv2.y, acc1[i]);
            acc0[i] = fma2(p3, wv3.x, acc0[i]); acc1[i] = fma2(p3, wv3.y, acc1[i]);
        }
    }

    float4 as4 = ((const float4*)att_src)[cg];
    float4 ad4 = ((const float4*)att_dst)[cg];
    float4* h4 = (float4*)g_h;
    int head = cg >> 3;

    #pragma unroll
    for (int i = 0; i < 8; i++) {
        float2 a = upk2(acc0[i]);
        float2 b = upk2(acc1[i]);
        float4 hv = make_float4(a.x, a.y, b.x, b.y);
        float ps = hv.x * as4.x + hv.y * as4.y + hv.z * as4.z + hv.w * as4.w;
        float pd = hv.x * ad4.x + hv.y * ad4.y + hv.z * ad4.z + hv.w * ad4.w;
        #pragma unroll
        for (int o = 4; o >= 1; o >>= 1) {
            ps += __shfl_xor_sync(0xffffffffu, ps, o);
            pd += __shfl_xor_sync(0xffffffffu, pd, o);
        }
        int grow = rowbase + rg * 8 + i;
        if (grow < n) {
            h4[grow * 32 + cg] = hv;
            if ((cg & 7) == 0) {
                g_asrc[grow * HH + head] = ps;
                g_adst[grow * HH + head] = pd;
            }
        }
    }
}

// ---------------- Kernel 2: histogram of dst ----------------
__global__ void hist_kernel(const void* __restrict__ ei, int E)
{
    int e = blockIdx.x * 256 + threadIdx.x;
    if (e < E) atomicAdd(&g_deg[edge_dst(ei, E, e)], 1);
}

// ---------------- Kernel 3a: per-block local exclusive scan -------------
__global__ __launch_bounds__(256)
void scan_local_kernel(int n)
{
    int i = blockIdx.x * 256 + threadIdx.x;
    int lane = threadIdx.x & 31;
    int wid  = threadIdx.x >> 5;
    int v = (i < n) ? g_deg[i] : 0;
    int inc = v;
    #pragma unroll
    for (int o = 1; o < 32; o <<= 1) {
        int t = __shfl_up_sync(0xffffffffu, inc, o);
        if (lane >= o) inc += t;
    }
    __shared__ int wsum[8];
    if (lane == 31) wsum[wid] = inc;
    __syncthreads();
    if (wid == 0) {
        int ws = (lane < 8) ? wsum[lane] : 0;
        #pragma unroll
        for (int o = 1; o < 8; o <<= 1) {
            int t = __shfl_up_sync(0xffffffffu, ws, o);
            if (lane >= o) ws += t;
        }
        if (lane < 8) wsum[lane] = ws;
    }
    __syncthreads();
    int warpbase = (wid == 0) ? 0 : wsum[wid - 1];
    int excl = warpbase + inc - v;
    if (i < n) g_rowoff[i] = excl;
    if (threadIdx.x == 255) g_bsum[blockIdx.x] = warpbase + inc;
}

// ---------------- Kernel 3b: fixup ----------------
__global__ __launch_bounds__(256)
void scan_fixup_kernel(int n, int nb)
{
    __shared__ int s_base;
    if (threadIdx.x < 32) {
        int b = 0;
        for (int j = threadIdx.x; j < blockIdx.x; j += 32) b += g_bsum[j];
        #pragma unroll
        for (int o = 16; o >= 1; o >>= 1)
            b += __shfl_xor_sync(0xffffffffu, b, o);
        if (threadIdx.x == 0) s_base = b;
    }
    __syncthreads();
    int i = blockIdx.x * 256 + threadIdx.x;
    if (i < n) {
        int r = g_rowoff[i] + s_base;
        g_rowoff[i] = r;
        g_cursor[i] = r;
    }
}

// ---------------- Kernel 4: scatter edges into CSR ----------------
__global__ void scatter_kernel(const void* __restrict__ ei, int E)
{
    int e = blockIdx.x * 256 + threadIdx.x;
    if (e < E) {
        int s = edge_src(ei, E, e);
        int d = edge_dst(ei, E, e);
        int pos = atomicAdd(&g_cursor[d], 1);
        g_srclist[pos] = s;
    }
}

// ---------------- Kernel 5: fused softmax-agg + GELU + LN + residual ----
// (R3/R4 proven version)
__global__ __launch_bounds__(256)
void agg_ln_kernel(const float* __restrict__ x,
                   const float* __restrict__ bias,
                   const float* __restrict__ gamma,
                   const float* __restrict__ beta,
                   float* __restrict__ out, int n)
{
    int node = blockIdx.x * 8 + (threadIdx.x >> 5);
    if (node >= n) return;
    int lane = threadIdx.x & 31;
    int hd8 = lane >> 3;
    int hd4 = lane & 3;
    int esub = lane >> 2;

    int beg = g_rowoff[node];
    int cnt = g_deg[node];

    float aself = g_asrc[node * HH + hd4];
    float adst4 = g_adst[node * HH + hd4];

    // Phase A: per-head max of a_src over {self} U neighbors
    float mx = aself;
    for (int k0 = 0; k0 < cnt; k0 += 8) {
        int k = k0 + esub;
        float v = -1e30f;
        if (k < cnt) {
            int s = g_srclist[beg + k];
            v = g_asrc[s * HH + hd4];
        }
        mx = fmaxf(mx, v);
    }
    mx = fmaxf(mx, __shfl_xor_sync(0xffffffffu, mx, 4));
    mx = fmaxf(mx, __shfl_xor_sync(0xffffffffu, mx, 8));
    mx = fmaxf(mx, __shfl_xor_sync(0xffffffffu, mx, 16));

    float mxh    = __shfl_sync(0xffffffffu, mx, hd8);
    float adst   = __shfl_sync(0xffffffffu, adst4, hd8);
    float aselfh = __shfl_sync(0xffffffffu, aself, hd8);
    float M = lrelu(mxh + adst);

    // Phase B: weighted aggregation
    const float4* h4 = (const float4*)g_h;
    float p0 = __expf(lrelu(aselfh + adst) - M);
    float4 hv = h4[node * 32 + lane];
    float4 accA = make_float4(p0 * hv.x, p0 * hv.y, p0 * hv.z, p0 * hv.w);
    float4 accB = make_float4(0.f, 0.f, 0.f, 0.f);
    float dA = p0, dB = 0.f;

    int k = 0;
    for (; k + 2 <= cnt; k += 2) {
        int sa = g_srclist[beg + k];
        int sb = g_srclist[beg + k + 1];
        float ea = g_asrc[sa * HH + hd8];
        float eb = g_asrc[sb * HH + hd8];
        float4 ha = h4[sa * 32 + lane];
        float4 hb = h4[sb * 32 + lane];
        float pa = __expf(lrelu(ea + adst) - M);
        float pb = __expf(lrelu(eb + adst) - M);
        dA += pa; dB += pb;
        accA.x = fmaf(pa, ha.x, accA.x); accA.y = fmaf(pa, ha.y, accA.y);
        accA.z = fmaf(pa, ha.z, accA.z); accA.w = fmaf(pa, ha.w, accA.w);
        accB.x = fmaf(pb, hb.x, accB.x); accB.y = fmaf(pb, hb.y, accB.y);
        accB.z = fmaf(pb, hb.z, accB.z); accB.w = fmaf(pb, hb.w, accB.w);
    }
    if (k < cnt) {
        int sa = g_srclist[beg + k];
        float ea = g_asrc[sa * HH + hd8];
        float4 ha = h4[sa * 32 + lane];
        float pa = __expf(lrelu(ea + adst) - M);
        dA += pa;
        accA.x = fmaf(pa, ha.x, accA.x); accA.y = fmaf(pa, ha.y, accA.y);
        accA.z = fmaf(pa, ha.z, accA.z); accA.w = fmaf(pa, ha.w, accA.w);
    }

    float denom = dA + dB;
    float inv = 1.0f / denom;
    float4 bi = ((const float4*)bias)[lane];
    float4 o = make_float4(fmaf(accA.x + accB.x, inv, bi.x),
                           fmaf(accA.y + accB.y, inv, bi.y),
                           fmaf(accA.z + accB.z, inv, bi.z),
                           fmaf(accA.w + accB.w, inv, bi.w));

    const float RS2 = 0.70710678118654752f;
    float4 f;
    f.x = 0.5f * o.x * (1.0f + erff(o.x * RS2));
    f.y = 0.5f * o.y * (1.0f + erff(o.y * RS2));
    f.z = 0.5f * o.z * (1.0f + erff(o.z * RS2));
    f.w = 0.5f * o.w * (1.0f + erff(o.w * RS2));

    float s1 = f.x + f.y + f.z + f.w;
    float s2 = f.x * f.x + f.y * f.y + f.z * f.z + f.w * f.w;
    #pragma unroll
    for (int off = 16; off >= 1; off >>= 1) {
        s1 += __shfl_xor_sync(0xffffffffu, s1, off);
        s2 += __shfl_xor_sync(0xffffffffu, s2, off);
    }
    float mu  = s1 * (1.0f / 128.0f);
    float var = s2 * (1.0f / 128.0f) - mu * mu;
    float r = rsqrtf(var + LN_EPS);

    float4 gm = ((const float4*)gamma)[lane];
    float4 bt = ((const float4*)beta)[lane];
    float4 xv = ((const float4*)x)[node * 32 + lane];
    float4 res;
    res.x = (f.x - mu) * r * gm.x + bt.x + xv.x;
    res.y = (f.y - mu) * r * gm.y + bt.y + xv.y;
    res.z = (f.z - mu) * r * gm.z + bt.z + xv.z;
    res.w = (f.w - mu) * r * gm.w + bt.w + xv.w;
    ((float4*)out)[node * 32 + lane] = res;
}

// ---------------- launch ----------------
extern "C" void kernel_launch(void* const* d_in, const int* in_sizes, int n_in,
                              void* d_out, int out_size)
{
    const float* x       = (const float*)d_in[0];
    const void*  ei      = d_in[1];
    const float* W       = (const float*)d_in[2];
    const float* att_src = (const float*)d_in[3];
    const float* att_dst = (const float*)d_in[4];
    const float* bias    = (const float*)d_in[5];
    const float* gamma   = (const float*)d_in[6];
    const float* beta    = (const float*)d_in[7];
    float*       out     = (float*)d_out;

    int n = in_sizes[0] / DD;     // 50000
    int E = in_sizes[1] / 2;      // 600000
    int nb = (n + 255) / 256;     // 196

    const int GEMM_SMEM = (128 * 128 + 64 * 128) * 4;  // 96KB
    cudaFuncSetAttribute(gemm_kernel, cudaFuncAttributeMaxDynamicSharedMemorySize, GEMM_SMEM);

    detect_zero_kernel<<<nb, 256>>>((const int*)ei, E, n);
    gemm_kernel<<<(n + 63) / 64, 256, GEMM_SMEM>>>(x, W, att_src, att_dst, n);
    hist_kernel<<<(E + 255) / 256, 256>>>(ei, E);
    scan_local_kernel<<<nb, 256>>>(n);
    scan_fixup_kernel<<<nb, 256>>>(n, nb);
    scatter_kernel<<<(E + 255) / 256, 256>>>(ei, E);
    agg_ln_kernel<<<(n + 7) / 8, 256>>>(x, bias, gamma, beta, out, n);
}

// round 10
// speedup vs baseline: 1.1475x; 1.0690x over previous
#include <cuda_runtime.h>
#include <cuda_bf16.h>
#include <math.h>

#define NN_MAX 50000
#define EE_MAX 600000
#define DD 128
#define HH 4
#define CC 32
#define NEG_SLOPE 0.2f
#define LN_EPS 1e-5f
#define NB_MAX 256

// ---------------- device scratch ----------------
static __device__ float g_h[NN_MAX * DD];
static __device__ float g_asrc[NN_MAX * HH];
static __device__ float g_adst[NN_MAX * HH];
static __device__ int   g_deg[NN_MAX];
static __device__ int   g_rowoff[NN_MAX];
static __device__ int   g_cursor[NN_MAX];
static __device__ int   g_srclist[EE_MAX];
static __device__ int   g_bsum[NB_MAX];
static __device__ int   g_is64;

// ---------------- f32x2 helpers ----------------
__device__ __forceinline__ unsigned long long pk2(float lo, float hi) {
    unsigned long long r;
    asm("mov.b64 %0, {%1, %2};" : "=l"(r) : "f"(lo), "f"(hi));
    return r;
}
__device__ __forceinline__ unsigned long long fma2(unsigned long long a,
                                                   unsigned long long b,
                                                   unsigned long long c) {
    unsigned long long d;
    asm("fma.rn.f32x2 %0, %1, %2, %3;" : "=l"(d) : "l"(a), "l"(b), "l"(c));
    return d;
}
__device__ __forceinline__ float2 upk2(unsigned long long v) {
    float lo, hi;
    asm("mov.b64 {%0, %1}, %2;" : "=f"(lo), "=f"(hi) : "l"(v));
    return make_float2(lo, hi);
}
__device__ __forceinline__ float lrelu(float v) {
    return (v > 0.f) ? v : v * NEG_SLOPE;
}

// ---------------- Kernel 0: zero degrees + detect dtype ----------------
__global__ void detect_zero_kernel(const int* __restrict__ ei32, int E, int n)
{
    int i = blockIdx.x * 256 + threadIdx.x;
    if (i < n) g_deg[i] = 0;
    if (blockIdx.x == 0) {
        int checks = 2 * E; if (checks > 4096) checks = 4096;
        int nz = 0;
        for (int j = threadIdx.x; j < checks; j += 256)
            if (ei32[2 * j + 1] != 0) nz = 1;
        #pragma unroll
        for (int o = 16; o >= 1; o >>= 1)
            nz |= __shfl_xor_sync(0xffffffffu, nz, o);
        __shared__ int s_nz[8];
        if ((threadIdx.x & 31) == 0) s_nz[threadIdx.x >> 5] = nz;
        __syncthreads();
        if (threadIdx.x == 0) {
            int a = 0;
            for (int w = 0; w < 8; w++) a |= s_nz[w];
            g_is64 = (a == 0) ? 1 : 0;
        }
    }
}

__device__ __forceinline__ int edge_src(const void* ei, int E, int e) {
    if (g_is64) return (int)((const long long*)ei)[e];
    return ((const int*)ei)[e];
}
__device__ __forceinline__ int edge_dst(const void* ei, int E, int e) {
    if (g_is64) return (int)((const long long*)ei)[E + e];
    return ((const int*)ei)[E + e];
}

// ---------------- Kernel 1: h = x @ W + fused attention logits ----------
// (R8 proven v1b — LDS.128 x broadcasts)
__global__ __launch_bounds__(256, 2)
void gemm_kernel(const float* __restrict__ x, const float* __restrict__ W,
                 const float* __restrict__ att_src, const float* __restrict__ att_dst,
                 int n)
{
    extern __shared__ float smem[];
    float* ws = smem;              // [128][128] = 64KB
    float* xs = smem + 128 * 128;  // [64][128]  = 32KB

    int rowbase = blockIdx.x * 64;

    const float4* W4 = (const float4*)W;
    float4* ws4 = (float4*)ws;
    #pragma unroll
    for (int t = threadIdx.x; t < 4096; t += 256) ws4[t] = W4[t];

    float4* xs4 = (float4*)xs;
    const float4* x4in = (const float4*)x;
    #pragma unroll
    for (int t = threadIdx.x; t < 2048; t += 256) {
        int r = t >> 5, k4 = t & 31;
        int grow = rowbase + r;
        float4 v = make_float4(0.f, 0.f, 0.f, 0.f);
        if (grow < n) v = x4in[grow * 32 + k4];
        xs4[r * 32 + k4] = v;
    }
    __syncthreads();

    int rg = threadIdx.x >> 5;
    int cg = threadIdx.x & 31;

    unsigned long long acc0[8], acc1[8];
    #pragma unroll
    for (int i = 0; i < 8; i++) { acc0[i] = 0ull; acc1[i] = 0ull; }

    const float* xrow = xs + rg * 8 * 128;
    const ulonglong2* ws2 = (const ulonglong2*)ws;

    #pragma unroll 4
    for (int k4 = 0; k4 < 32; k4++) {
        ulonglong2 wv0 = ws2[(k4 * 4 + 0) * 32 + cg];
        ulonglong2 wv1 = ws2[(k4 * 4 + 1) * 32 + cg];
        ulonglong2 wv2 = ws2[(k4 * 4 + 2) * 32 + cg];
        ulonglong2 wv3 = ws2[(k4 * 4 + 3) * 32 + cg];
        #pragma unroll
        for (int i = 0; i < 8; i++) {
            float4 xv = *(const float4*)(xrow + i * 128 + k4 * 4);
            unsigned long long p0 = pk2(xv.x, xv.x);
            unsigned long long p1 = pk2(xv.y, xv.y);
            unsigned long long p2 = pk2(xv.z, xv.z);
            unsigned long long p3 = pk2(xv.w, xv.w);
            acc0[i] = fma2(p0, wv0.x, acc0[i]); acc1[i] = fma2(p0, wv0.y, acc1[i]);
            acc0[i] = fma2(p1, wv1.x, acc0[i]); acc1[i] = fma2(p1, wv1.y, acc1[i]);
            acc0[i] = fma2(p2, wv2.x, acc0[i]); acc1[i] = fma2(p2, wv2.y, acc1[i]);
            acc0[i] = fma2(p3, wv3.x, acc0[i]); acc1[i] = fma2(p3, wv3.y, acc1[i]);
        }
    }

    float4 as4 = ((const float4*)att_src)[cg];
    float4 ad4 = ((const float4*)att_dst)[cg];
    float4* h4 = (float4*)g_h;
    int head = cg >> 3;

    #pragma unroll
    for (int i = 0; i < 8; i++) {
        float2 a = upk2(acc0[i]);
        float2 b = upk2(acc1[i]);
        float4 hv = make_float4(a.x, a.y, b.x, b.y);
        float ps = hv.x * as4.x + hv.y * as4.y + hv.z * as4.z + hv.w * as4.w;
        float pd = hv.x * ad4.x + hv.y * ad4.y + hv.z * ad4.z + hv.w * ad4.w;
        #pragma unroll
        for (int o = 4; o >= 1; o >>= 1) {
            ps += __shfl_xor_sync(0xffffffffu, ps, o);
            pd += __shfl_xor_sync(0xffffffffu, pd, o);
        }
        int grow = rowbase + rg * 8 + i;
        if (grow < n) {
            h4[grow * 32 + cg] = hv;
            if ((cg & 7) == 0) {
                g_asrc[grow * HH + head] = ps;
                g_adst[grow * HH + head] = pd;
            }
        }
    }
}

// ---------------- Kernel 2: histogram of dst ----------------
__global__ void hist_kernel(const void* __restrict__ ei, int E)
{
    int e = blockIdx.x * 256 + threadIdx.x;
    if (e < E) atomicAdd(&g_deg[edge_dst(ei, E, e)], 1);
}

// ---------------- Kernel 3a: per-block local exclusive scan -------------
__global__ __launch_bounds__(256)
void scan_local_kernel(int n)
{
    int i = blockIdx.x * 256 + threadIdx.x;
    int lane = threadIdx.x & 31;
    int wid  = threadIdx.x >> 5;
    int v = (i < n) ? g_deg[i] : 0;
    int inc = v;
    #pragma unroll
    for (int o = 1; o < 32; o <<= 1) {
        int t = __shfl_up_sync(0xffffffffu, inc, o);
        if (lane >= o) inc += t;
    }
    __shared__ int wsum[8];
    if (lane == 31) wsum[wid] = inc;
    __syncthreads();
    if (wid == 0) {
        int ws = (lane < 8) ? wsum[lane] : 0;
        #pragma unroll
        for (int o = 1; o < 8; o <<= 1) {
            int t = __shfl_up_sync(0xffffffffu, ws, o);
            if (lane >= o) ws += t;
        }
        if (lane < 8) wsum[lane] = ws;
    }
    __syncthreads();
    int warpbase = (wid == 0) ? 0 : wsum[wid - 1];
    int excl = warpbase + inc - v;
    if (i < n) g_rowoff[i] = excl;
    if (threadIdx.x == 255) g_bsum[blockIdx.x] = warpbase + inc;
}

// ---------------- Kernel 3b: fixup ----------------
__global__ __launch_bounds__(256)
void scan_fixup_kernel(int n, int nb)
{
    __shared__ int s_base;
    if (threadIdx.x < 32) {
        int b = 0;
        for (int j = threadIdx.x; j < blockIdx.x; j += 32) b += g_bsum[j];
        #pragma unroll
        for (int o = 16; o >= 1; o >>= 1)
            b += __shfl_xor_sync(0xffffffffu, b, o);
        if (threadIdx.x == 0) s_base = b;
    }
    __syncthreads();
    int i = blockIdx.x * 256 + threadIdx.x;
    if (i < n) {
        int r = g_rowoff[i] + s_base;
        g_rowoff[i] = r;
        g_cursor[i] = r;
    }
}

// ---------------- Kernel 4: scatter edges into CSR ----------------
__global__ void scatter_kernel(const void* __restrict__ ei, int E)
{
    int e = blockIdx.x * 256 + threadIdx.x;
    if (e < E) {
        int s = edge_src(ei, E, e);
        int d = edge_dst(ei, E, e);
        int pos = atomicAdd(&g_cursor[d], 1);
        g_srclist[pos] = s;
    }
}

// ---------------- Kernel 5: fused softmax-agg + GELU + LN + residual ----
// (R3/R4 proven version)
__global__ __launch_bounds__(256)
void agg_ln_kernel(const float* __restrict__ x,
                   const float* __restrict__ bias,
                   const float* __restrict__ gamma,
                   const float* __restrict__ beta,
                   float* __restrict__ out, int n)
{
    int node = blockIdx.x * 8 + (threadIdx.x >> 5);
    if (node >= n) return;
    int lane = threadIdx.x & 31;
    int hd8 = lane >> 3;
    int hd4 = lane & 3;
    int esub = lane >> 2;

    int beg = g_rowoff[node];
    int cnt = g_deg[node];

    float aself = g_asrc[node * HH + hd4];
    float adst4 = g_adst[node * HH + hd4];

    // Phase A: per-head max of a_src over {self} U neighbors
    float mx = aself;
    for (int k0 = 0; k0 < cnt; k0 += 8) {
        int k = k0 + esub;
        float v = -1e30f;
        if (k < cnt) {
            int s = g_srclist[beg + k];
            v = g_asrc[s * HH + hd4];
        }
        mx = fmaxf(mx, v);
    }
    mx = fmaxf(mx, __shfl_xor_sync(0xffffffffu, mx, 4));
    mx = fmaxf(mx, __shfl_xor_sync(0xffffffffu, mx, 8));
    mx = fmaxf(mx, __shfl_xor_sync(0xffffffffu, mx, 16));

    float mxh    = __shfl_sync(0xffffffffu, mx, hd8);
    float adst   = __shfl_sync(0xffffffffu, adst4, hd8);
    float aselfh = __shfl_sync(0xffffffffu, aself, hd8);
    float M = lrelu(mxh + adst);

    // Phase B: weighted aggregation
    const float4* h4 = (const float4*)g_h;
    float p0 = __expf(lrelu(aselfh + adst) - M);
    float4 hv = h4[node * 32 + lane];
    float4 accA = make_float4(p0 * hv.x, p0 * hv.y, p0 * hv.z, p0 * hv.w);
    float4 accB = make_float4(0.f, 0.f, 0.f, 0.f);
    float dA = p0, dB = 0.f;

    int k = 0;
    for (; k + 2 <= cnt; k += 2) {
        int sa = g_srclist[beg + k];
        int sb = g_srclist[beg + k + 1];
        float ea = g_asrc[sa * HH + hd8];
        float eb = g_asrc[sb * HH + hd8];
        float4 ha = h4[sa * 32 + lane];
        float4 hb = h4[sb * 32 + lane];
        float pa = __expf(lrelu(ea + adst) - M);
        float pb = __expf(lrelu(eb + adst) - M);
        dA += pa; dB += pb;
        accA.x = fmaf(pa, ha.x, accA.x); accA.y = fmaf(pa, ha.y, accA.y);
        accA.z = fmaf(pa, ha.z, accA.z); accA.w = fmaf(pa, ha.w, accA.w);
        accB.x = fmaf(pb, hb.x, accB.x); accB.y = fmaf(pb, hb.y, accB.y);
        accB.z = fmaf(pb, hb.z, accB.z); accB.w = fmaf(pb, hb.w, accB.w);
    }
    if (k < cnt) {
        int sa = g_srclist[beg + k];
        float ea = g_asrc[sa * HH + hd8];
        float4 ha = h4[sa * 32 + lane];
        float pa = __expf(lrelu(ea + adst) - M);
        dA += pa;
        accA.x = fmaf(pa, ha.x, accA.x); accA.y = fmaf(pa, ha.y, accA.y);
        accA.z = fmaf(pa, ha.z, accA.z); accA.w = fmaf(pa, ha.w, accA.w);
    }

    float denom = dA + dB;
    float inv = 1.0f / denom;
    float4 bi = ((const float4*)bias)[lane];
    float4 o = make_float4(fmaf(accA.x + accB.x, inv, bi.x),
                           fmaf(accA.y + accB.y, inv, bi.y),
                           fmaf(accA.z + accB.z, inv, bi.z),
                           fmaf(accA.w + accB.w, inv, bi.w));

    const float RS2 = 0.70710678118654752f;
    float4 f;
    f.x = 0.5f * o.x * (1.0f + erff(o.x * RS2));
    f.y = 0.5f * o.y * (1.0f + erff(o.y * RS2));
    f.z = 0.5f * o.z * (1.0f + erff(o.z * RS2));
    f.w = 0.5f * o.w * (1.0f + erff(o.w * RS2));

    float s1 = f.x + f.y + f.z + f.w;
    float s2 = f.x * f.x + f.y * f.y + f.z * f.z + f.w * f.w;
    #pragma unroll
    for (int off = 16; off >= 1; off >>= 1) {
        s1 += __shfl_xor_sync(0xffffffffu, s1, off);
        s2 += __shfl_xor_sync(0xffffffffu, s2, off);
    }
    float mu  = s1 * (1.0f / 128.0f);
    float var = s2 * (1.0f / 128.0f) - mu * mu;
    float r = rsqrtf(var + LN_EPS);

    float4 gm = ((const float4*)gamma)[lane];
    float4 bt = ((const float4*)beta)[lane];
    float4 xv = ((const float4*)x)[node * 32 + lane];
    float4 res;
    res.x = (f.x - mu) * r * gm.x + bt.x + xv.x;
    res.y = (f.y - mu) * r * gm.y + bt.y + xv.y;
    res.z = (f.z - mu) * r * gm.z + bt.z + xv.z;
    res.w = (f.w - mu) * r * gm.w + bt.w + xv.w;
    ((float4*)out)[node * 32 + lane] = res;
}

// ---------------- launch: fork gemm || CSR-build, join at agg ----------
extern "C" void kernel_launch(void* const* d_in, const int* in_sizes, int n_in,
                              void* d_out, int out_size)
{
    const float* x       = (const float*)d_in[0];
    const void*  ei      = d_in[1];
    const float* W       = (const float*)d_in[2];
    const float* att_src = (const float*)d_in[3];
    const float* att_dst = (const float*)d_in[4];
    const float* bias    = (const float*)d_in[5];
    const float* gamma   = (const float*)d_in[6];
    const float* beta    = (const float*)d_in[7];
    float*       out     = (float*)d_out;

    int n = in_sizes[0] / DD;     // 50000
    int E = in_sizes[1] / 2;      // 600000
    int nb = (n + 255) / 256;     // 196

    const int GEMM_SMEM = (128 * 128 + 64 * 128) * 4;  // 96KB
    static bool s_init = false;
    static cudaStream_t s2;
    static cudaEvent_t evFork, evJoin;
    if (!s_init) {
        cudaFuncSetAttribute(gemm_kernel,
                             cudaFuncAttributeMaxDynamicSharedMemorySize, GEMM_SMEM);
        cudaStreamCreateWithFlags(&s2, cudaStreamNonBlocking);
        cudaEventCreateWithFlags(&evFork, cudaEventDisableTiming);
        cudaEventCreateWithFlags(&evJoin, cudaEventDisableTiming);
        s_init = true;
    }

    // Fork: side stream joins the capture via event dependency.
    cudaEventRecord(evFork, 0);
    cudaStreamWaitEvent(s2, evFork, 0);

    // Chain A (default stream): GEMM + attention logits
    gemm_kernel<<<(n + 63) / 64, 256, GEMM_SMEM>>>(x, W, att_src, att_dst, n);

    // Chain B (side stream): CSR build from edge_index
    detect_zero_kernel<<<nb, 256, 0, s2>>>((const int*)ei, E, n);
    hist_kernel<<<(E + 255) / 256, 256, 0, s2>>>(ei, E);
    scan_local_kernel<<<nb, 256, 0, s2>>>(n);
    scan_fixup_kernel<<<nb, 256, 0, s2>>>(n, nb);
    scatter_kernel<<<(E + 255) / 256, 256, 0, s2>>>(ei, E);

    // Join: agg depends on both chains.
    cudaEventRecord(evJoin, s2);
    cudaStreamWaitEvent(0, evJoin, 0);

    agg_ln_kernel<<<(n + 7) / 8, 256>>>(x, bias, gamma, beta, out, n);
}